// round 2
// baseline (speedup 1.0000x reference)
#include <cuda_runtime.h>

// out[b,c] = exp( sum_s x[b, chunk_map[c,s]] * wSupp[c,s] )
// B=4096, NCLASS=1000, NSUPP=64, NCHUNK=4096

#define NCLASS 1000
#define NSUPP  64
#define NCHUNK 4096
#define BATCH  4096
#define NB     8       // batch rows per CTA
#define THREADS 1024

// Packed (idx, w) pairs, transposed to [s2][class] so the hot loop's LDG is
// coalesced across lanes (lane = class). Each int4 holds 2 s-steps.
// Entries are bank-conflict-scheduled: counting-sorted by idx%8 (LDS bank
// group) and rotated by (c%8)*8 so the 8 lanes of each LDS phase hit
// ~distinct bank groups at every step.
__device__ int4 g_packed[(NSUPP / 2) * NCLASS];

__global__ void pack_kernel(const float* __restrict__ w,
                            const int* __restrict__ cmap) {
    int c = blockIdx.x * blockDim.x + threadIdx.x;
    if (c >= NCLASS) return;

    int   idxs[NSUPP];
    float ws[NSUPP];
    int cnt[8] = {0, 0, 0, 0, 0, 0, 0, 0};

    for (int s = 0; s < NSUPP; ++s) {
        int idx = cmap[c * NSUPP + s];
        idxs[s] = idx;
        ws[s]   = w[c * NSUPP + s];
        cnt[idx & 7]++;
    }
    // exclusive prefix -> start position of each bank group
    int pos[8];
    int run = 0;
    for (int g = 0; g < 8; ++g) { pos[g] = run; run += cnt[g]; }

    // counting sort by bank group
    int order[NSUPP];
    for (int s = 0; s < NSUPP; ++s) {
        int g = idxs[s] & 7;
        order[pos[g]++] = s;
    }

    // rotate by (c%8)*8 entries, pack pairs into [s2][class]
    int rot = (c & 7) * 8;
    for (int j2 = 0; j2 < NSUPP / 2; ++j2) {
        int e0 = order[(2 * j2 + rot) & (NSUPP - 1)];
        int e1 = order[(2 * j2 + 1 + rot) & (NSUPP - 1)];
        int4 p;
        p.x = idxs[e0];
        p.y = __float_as_int(ws[e0]);
        p.z = idxs[e1];
        p.w = __float_as_int(ws[e1]);
        g_packed[j2 * NCLASS + c] = p;
    }
}

__global__ void __launch_bounds__(THREADS, 1)
supp_kernel(const float* __restrict__ x, float* __restrict__ out) {
    // Two separate float4 tiles so each gather's bank group is idx&7
    // (full 8-bin spread) and tile-fill STS.128 is conflict-free.
    extern __shared__ float4 smem[];
    float4* xs_lo = smem;           // x[b0..b0+3][idx]
    float4* xs_hi = smem + NCHUNK;  // x[b0+4..b0+7][idx]

    const int b0 = blockIdx.x * NB;

    // --- Stage x tile: 8 rows x 4096 floats = 128 KB ---
    for (int i = threadIdx.x; i < NCHUNK; i += THREADS) {
        const float* xb = x + (size_t)b0 * NCHUNK + i;
        float t0 = xb[0 * NCHUNK];
        float t1 = xb[1 * NCHUNK];
        float t2 = xb[2 * NCHUNK];
        float t3 = xb[3 * NCHUNK];
        float t4 = xb[4 * NCHUNK];
        float t5 = xb[5 * NCHUNK];
        float t6 = xb[6 * NCHUNK];
        float t7 = xb[7 * NCHUNK];
        xs_lo[i] = make_float4(t0, t1, t2, t3);
        xs_hi[i] = make_float4(t4, t5, t6, t7);
    }
    __syncthreads();

    // --- Gather + dot: thread = class, 8 batch rows per thread ---
    // (class c lands on lane c%32, so phase-offset = c%8 matches pack rotation)
    for (int c = threadIdx.x; c < NCLASS; c += THREADS) {
        float a0 = 0.f, a1 = 0.f, a2 = 0.f, a3 = 0.f;
        float a4 = 0.f, a5 = 0.f, a6 = 0.f, a7 = 0.f;
#pragma unroll 2
        for (int s2 = 0; s2 < NSUPP / 2; ++s2) {
            int4 p = g_packed[s2 * NCLASS + c];  // coalesced LDG.128

            float w0 = __int_as_float(p.y);
            float4 lo = xs_lo[p.x];
            float4 hi = xs_hi[p.x];
            a0 = fmaf(lo.x, w0, a0);
            a1 = fmaf(lo.y, w0, a1);
            a2 = fmaf(lo.z, w0, a2);
            a3 = fmaf(lo.w, w0, a3);
            a4 = fmaf(hi.x, w0, a4);
            a5 = fmaf(hi.y, w0, a5);
            a6 = fmaf(hi.z, w0, a6);
            a7 = fmaf(hi.w, w0, a7);

            float w1 = __int_as_float(p.w);
            lo = xs_lo[p.z];
            hi = xs_hi[p.z];
            a0 = fmaf(lo.x, w1, a0);
            a1 = fmaf(lo.y, w1, a1);
            a2 = fmaf(lo.z, w1, a2);
            a3 = fmaf(lo.w, w1, a3);
            a4 = fmaf(hi.x, w1, a4);
            a5 = fmaf(hi.y, w1, a5);
            a6 = fmaf(hi.z, w1, a6);
            a7 = fmaf(hi.w, w1, a7);
        }

        float* o = out + (size_t)b0 * NCLASS + c;
        o[0 * NCLASS] = __expf(a0);
        o[1 * NCLASS] = __expf(a1);
        o[2 * NCLASS] = __expf(a2);
        o[3 * NCLASS] = __expf(a3);
        o[4 * NCLASS] = __expf(a4);
        o[5 * NCLASS] = __expf(a5);
        o[6 * NCLASS] = __expf(a6);
        o[7 * NCLASS] = __expf(a7);
    }
}

extern "C" void kernel_launch(void* const* d_in, const int* in_sizes, int n_in,
                              void* d_out, int out_size) {
    const float* x    = (const float*)d_in[0];  // [4096, 4096] f32
    const float* w    = (const float*)d_in[1];  // [1000, 64]   f32
    const int*   cmap = (const int*)d_in[2];    // [1000, 64]   i32
    float*       out  = (float*)d_out;          // [4096, 1000] f32

    (void)in_sizes; (void)n_in; (void)out_size;

    static const size_t smem_bytes = 2 * NCHUNK * sizeof(float4);  // 128 KB
    cudaFuncSetAttribute(supp_kernel,
                         cudaFuncAttributeMaxDynamicSharedMemorySize,
                         (int)smem_bytes);

    pack_kernel<<<(NCLASS + 255) / 256, 256>>>(w, cmap);
    supp_kernel<<<BATCH / NB, THREADS, smem_bytes>>>(x, out);
}

// round 3
// speedup vs baseline: 1.4120x; 1.4120x over previous
#include <cuda_runtime.h>

// out[b,c] = exp( sum_s x[b, chunk_map[c,s]] * wSupp[c,s] )
// B=4096, NCLASS=1000, NSUPP=64, NCHUNK=4096

#define NCLASS 1000
#define NSUPP  64
#define NCHUNK 4096
#define BATCH  4096
#define NB     8       // batch rows per CTA
#define THREADS 1024

// Packed (idx, w) pairs, transposed to [s2][class] so the hot loop's LDG is
// coalesced across lanes (lane = class). Each int4 holds 2 s-steps.
// Entries are bank-conflict-scheduled: counting-sorted by idx%8 (LDS bank
// group) and rotated by (c%8)*8 so the 8 lanes of each LDS phase hit
// ~distinct bank groups at every step.
__device__ int4 g_packed[(NSUPP / 2) * NCLASS];

// Array-free parallel pack: one thread per (class, bank-group).
// Pass 1 computes this group's base offset in the per-class counting sort;
// pass 2 scatters the group's entries straight to their final packed slots.
// cmap rows are re-read 8x but stay L1/L2 resident.
__global__ void pack_kernel(const float* __restrict__ w,
                            const int* __restrict__ cmap) {
    int t = blockIdx.x * blockDim.x + threadIdx.x;
    if (t >= NCLASS * 8) return;
    int c = t >> 3;
    int g = t & 7;

    const int*   row  = cmap + c * NSUPP;
    const float* wrow = w + c * NSUPP;
    const int rot = (c & 7) * 8;

    // base = #entries in groups < g (exclusive prefix of counting sort)
    int base = 0;
#pragma unroll
    for (int s = 0; s < NSUPP; ++s)
        base += ((row[s] & 7) < g);

    // scatter this group's entries (encounter order) to packed positions
    int2* outp = (int2*)g_packed;
    int i = 0;
#pragma unroll
    for (int s = 0; s < NSUPP; ++s) {
        int idx = row[s];
        if ((idx & 7) == g) {
            int slot = base + i;            // position in sorted order
            int p    = (slot - rot) & (NSUPP - 1);  // packed position
            int j2   = p >> 1;
            outp[(j2 * NCLASS + c) * 2 + (p & 1)] =
                make_int2(idx, __float_as_int(wrow[s]));
            ++i;
        }
    }
}

__global__ void __launch_bounds__(THREADS, 1)
supp_kernel(const float* __restrict__ x, float* __restrict__ out) {
    // Two separate float4 tiles so each gather's bank group is idx&7
    // (full 8-bin spread) and tile-fill STS.128 is conflict-free.
    extern __shared__ float4 smem[];
    float4* xs_lo = smem;           // x[b0..b0+3][idx]
    float4* xs_hi = smem + NCHUNK;  // x[b0+4..b0+7][idx]

    const int b0 = blockIdx.x * NB;

    // --- Stage x tile: 8 rows x 4096 floats = 128 KB ---
    for (int i = threadIdx.x; i < NCHUNK; i += THREADS) {
        const float* xb = x + (size_t)b0 * NCHUNK + i;
        float t0 = xb[0 * NCHUNK];
        float t1 = xb[1 * NCHUNK];
        float t2 = xb[2 * NCHUNK];
        float t3 = xb[3 * NCHUNK];
        float t4 = xb[4 * NCHUNK];
        float t5 = xb[5 * NCHUNK];
        float t6 = xb[6 * NCHUNK];
        float t7 = xb[7 * NCHUNK];
        xs_lo[i] = make_float4(t0, t1, t2, t3);
        xs_hi[i] = make_float4(t4, t5, t6, t7);
    }
    __syncthreads();

    // --- Gather + dot: thread = class, 8 batch rows per thread ---
    // (class c lands on lane c%32, so phase-offset = c%8 matches pack rotation)
    for (int c = threadIdx.x; c < NCLASS; c += THREADS) {
        float a0 = 0.f, a1 = 0.f, a2 = 0.f, a3 = 0.f;
        float a4 = 0.f, a5 = 0.f, a6 = 0.f, a7 = 0.f;
#pragma unroll 2
        for (int s2 = 0; s2 < NSUPP / 2; ++s2) {
            int4 p = g_packed[s2 * NCLASS + c];  // coalesced LDG.128

            float w0 = __int_as_float(p.y);
            float4 lo = xs_lo[p.x];
            float4 hi = xs_hi[p.x];
            a0 = fmaf(lo.x, w0, a0);
            a1 = fmaf(lo.y, w0, a1);
            a2 = fmaf(lo.z, w0, a2);
            a3 = fmaf(lo.w, w0, a3);
            a4 = fmaf(hi.x, w0, a4);
            a5 = fmaf(hi.y, w0, a5);
            a6 = fmaf(hi.z, w0, a6);
            a7 = fmaf(hi.w, w0, a7);

            float w1 = __int_as_float(p.w);
            lo = xs_lo[p.z];
            hi = xs_hi[p.z];
            a0 = fmaf(lo.x, w1, a0);
            a1 = fmaf(lo.y, w1, a1);
            a2 = fmaf(lo.z, w1, a2);
            a3 = fmaf(lo.w, w1, a3);
            a4 = fmaf(hi.x, w1, a4);
            a5 = fmaf(hi.y, w1, a5);
            a6 = fmaf(hi.z, w1, a6);
            a7 = fmaf(hi.w, w1, a7);
        }

        float* o = out + (size_t)b0 * NCLASS + c;
        o[0 * NCLASS] = __expf(a0);
        o[1 * NCLASS] = __expf(a1);
        o[2 * NCLASS] = __expf(a2);
        o[3 * NCLASS] = __expf(a3);
        o[4 * NCLASS] = __expf(a4);
        o[5 * NCLASS] = __expf(a5);
        o[6 * NCLASS] = __expf(a6);
        o[7 * NCLASS] = __expf(a7);
    }
}

extern "C" void kernel_launch(void* const* d_in, const int* in_sizes, int n_in,
                              void* d_out, int out_size) {
    const float* x    = (const float*)d_in[0];  // [4096, 4096] f32
    const float* w    = (const float*)d_in[1];  // [1000, 64]   f32
    const int*   cmap = (const int*)d_in[2];    // [1000, 64]   i32
    float*       out  = (float*)d_out;          // [4096, 1000] f32

    (void)in_sizes; (void)n_in; (void)out_size;

    static const size_t smem_bytes = 2 * NCHUNK * sizeof(float4);  // 128 KB
    cudaFuncSetAttribute(supp_kernel,
                         cudaFuncAttributeMaxDynamicSharedMemorySize,
                         (int)smem_bytes);

    pack_kernel<<<(NCLASS * 8 + 255) / 256, 256>>>(w, cmap);
    supp_kernel<<<BATCH / NB, THREADS, smem_bytes>>>(x, out);
}